// round 3
// baseline (speedup 1.0000x reference)
#include <cuda_runtime.h>
#include <cstdint>

// GaborLayer: out[p, c] = sin(x_p . W_c + b_c) * exp(-0.5 * ||x_p - mu_c||^2 * gamma_c)
// x: (B*N, 3) = (262144, 3), 256 output channels, out fp32 (B*N, 256).
//
// Refactor: exponent*log2(e) = g*(x.mu) - 0.5*g*||x||^2 - 0.5*g*||mu||^2, g = gamma*log2e
//   -> single ex2.approx per element. sin via MUFU sin.approx (__sinf).
//
// Layout: blockDim=256, threadIdx.x = channel. Per-channel constants in registers.
// Points tiled TP=128 per iteration, staged in smem as float4 {x,y,z,x2}.
// Stores: 256 threads write one contiguous 1024B row per point (coalesced).

#define TP 128
#define NCH 256

__global__ __launch_bounds__(NCH) void gabor_kernel(
    const float* __restrict__ x,
    const float* __restrict__ W,
    const float* __restrict__ b,
    const float* __restrict__ mu,
    const float* __restrict__ gamma,
    float* __restrict__ out,
    int npts)
{
    __shared__ float  raw[TP * 3];
    __shared__ float4 pts[TP];

    const int c = threadIdx.x;

    // ---- per-channel constants (registers, loaded once per block) ----
    const float w0 = W[c * 3 + 0];
    const float w1 = W[c * 3 + 1];
    const float w2 = W[c * 3 + 2];
    const float bb = b[c];
    const float m0 = mu[c * 3 + 0];
    const float m1 = mu[c * 3 + 1];
    const float m2 = mu[c * 3 + 2];
    const float L2E = 1.4426950408889634f;
    const float g  = gamma[c] * L2E;
    const float a0 = g * m0;
    const float a1 = g * m1;
    const float a2 = g * m2;
    const float ah = -0.5f * g;
    const float cc = ah * (m0 * m0 + m1 * m1 + m2 * m2);

    const int ntiles = npts / TP;  // 262144 / 128 = 2048, exact for this problem

    for (int tile = blockIdx.x; tile < ntiles; tile += gridDim.x) {
        const int p0 = tile * TP;

        // ---- stage raw coords (384 floats), stride-3 smem access is conflict-free ----
        for (int i = c; i < TP * 3; i += NCH) raw[i] = x[(size_t)p0 * 3 + i];
        __syncthreads();
        if (c < TP) {
            float v0 = raw[c * 3 + 0];
            float v1 = raw[c * 3 + 1];
            float v2 = raw[c * 3 + 2];
            pts[c] = make_float4(v0, v1, v2, v0 * v0 + v1 * v1 + v2 * v2);
        }
        __syncthreads();

        float* o = out + (size_t)p0 * NCH + c;

        #pragma unroll 8
        for (int p = 0; p < TP; p++) {
            const float4 q = pts[p];  // broadcast LDS.128, no bank conflict
            float lin = fmaf(w0, q.x, fmaf(w1, q.y, fmaf(w2, q.z, bb)));
            float e   = fmaf(a0, q.x, fmaf(a1, q.y, fmaf(a2, q.z, fmaf(ah, q.w, cc))));
            float s   = __sinf(lin);        // MUFU SIN
            float t;
            asm("ex2.approx.f32 %0, %1;" : "=f"(t) : "f"(e));  // MUFU EX2
            o[(size_t)p * NCH] = s * t;
        }
        __syncthreads();  // protect smem before next tile's staging
    }
}

extern "C" void kernel_launch(void* const* d_in, const int* in_sizes, int n_in,
                              void* d_out, int out_size)
{
    const float* x     = (const float*)d_in[0];  // (4, 65536, 3)
    const float* W     = (const float*)d_in[1];  // (256, 3)
    const float* b     = (const float*)d_in[2];  // (256,)
    const float* mu    = (const float*)d_in[3];  // (256, 3)
    const float* gamma = (const float*)d_in[4];  // (256,)
    float* out = (float*)d_out;                  // (4, 65536, 256)

    const int npts   = in_sizes[0] / 3;          // 262144
    const int ntiles = npts / TP;                // 2048

    gabor_kernel<<<ntiles, NCH>>>(x, W, b, mu, gamma, out, npts);
}

// round 4
// speedup vs baseline: 1.0142x; 1.0142x over previous
#include <cuda_runtime.h>
#include <cstdint>

// GaborLayer: out[p, c] = sin(x_p . W_c + b_c) * exp(-0.5 * ||x_p - mu_c||^2 * gamma_c)
// 262144 points x 256 channels, fp32 out.
//
// R3: 4 channels/thread + STG.128, paired-channel math via fma.rn.f32x2 (FFMA2),
// TP=64 tiles (grid=4096) to kill the wave-quantization tail.
//
// exponent*log2e = a.x + ah*||x||^2 + cc,  a = g*mu, ah = -g/2, cc = ah*||mu||^2, g = gamma*log2e
// -> one ex2.approx per element; sin via MUFU __sinf.

#define TP  64
#define NCH 256

typedef unsigned long long u64;

__device__ __forceinline__ u64 pack2(float lo, float hi) {
    u64 r; asm("mov.b64 %0, {%1, %2};" : "=l"(r) : "f"(lo), "f"(hi)); return r;
}
__device__ __forceinline__ void unpack2(float& lo, float& hi, u64 v) {
    asm("mov.b64 {%0, %1}, %2;" : "=f"(lo), "=f"(hi) : "l"(v));
}
__device__ __forceinline__ u64 fma2(u64 a, u64 b, u64 c) {
    u64 d; asm("fma.rn.f32x2 %0, %1, %2, %3;" : "=l"(d) : "l"(a), "l"(b), "l"(c)); return d;
}

__global__ __launch_bounds__(NCH) void gabor_kernel(
    const float* __restrict__ x,
    const float* __restrict__ W,
    const float* __restrict__ b,
    const float* __restrict__ mu,
    const float* __restrict__ gamma,
    float* __restrict__ out)
{
    __shared__ float4 raw4[TP * 3 / 4];   // 48 float4 = 192 floats of raw coords
    __shared__ float4 pts[TP];            // {x, y, z, ||x||^2}

    const int tid = threadIdx.x;
    const int cg  = tid & 63;             // channel group: channels 4cg .. 4cg+3
    const int pl  = tid >> 6;             // point lane 0..3

    // ---- per-thread channel constants for 4 channels, packed into f32x2 pairs ----
    const float L2E = 1.4426950408889634f;
    float wv[3][4], bv[4], av[3][4], ahv[4], ccv[4];
    #pragma unroll
    for (int j = 0; j < 4; j++) {
        const int c = 4 * cg + j;
        const float m0 = mu[c * 3 + 0], m1 = mu[c * 3 + 1], m2 = mu[c * 3 + 2];
        const float g = gamma[c] * L2E;
        wv[0][j] = W[c * 3 + 0]; wv[1][j] = W[c * 3 + 1]; wv[2][j] = W[c * 3 + 2];
        bv[j] = b[c];
        av[0][j] = g * m0; av[1][j] = g * m1; av[2][j] = g * m2;
        ahv[j] = -0.5f * g;
        ccv[j] = ahv[j] * (m0 * m0 + m1 * m1 + m2 * m2);
    }
    const u64 wx01 = pack2(wv[0][0], wv[0][1]), wx23 = pack2(wv[0][2], wv[0][3]);
    const u64 wy01 = pack2(wv[1][0], wv[1][1]), wy23 = pack2(wv[1][2], wv[1][3]);
    const u64 wz01 = pack2(wv[2][0], wv[2][1]), wz23 = pack2(wv[2][2], wv[2][3]);
    const u64 b01  = pack2(bv[0], bv[1]),       b23  = pack2(bv[2], bv[3]);
    const u64 ax01 = pack2(av[0][0], av[0][1]), ax23 = pack2(av[0][2], av[0][3]);
    const u64 ay01 = pack2(av[1][0], av[1][1]), ay23 = pack2(av[1][2], av[1][3]);
    const u64 az01 = pack2(av[2][0], av[2][1]), az23 = pack2(av[2][2], av[2][3]);
    const u64 ah01 = pack2(ahv[0], ahv[1]),     ah23 = pack2(ahv[2], ahv[3]);
    const u64 cc01 = pack2(ccv[0], ccv[1]),     cc23 = pack2(ccv[2], ccv[3]);

    // ---- one tile of TP points per block ----
    const int p0 = blockIdx.x * TP;

    if (tid < TP * 3 / 4)
        raw4[tid] = ((const float4*)(x + (size_t)p0 * 3))[tid];
    __syncthreads();
    if (tid < TP) {
        const float* rf = (const float*)raw4;
        float v0 = rf[tid * 3 + 0], v1 = rf[tid * 3 + 1], v2 = rf[tid * 3 + 2];
        pts[tid] = make_float4(v0, v1, v2, v0 * v0 + v1 * v1 + v2 * v2);
    }
    __syncthreads();

    const int pbase = pl * (TP / 4);
    float4* o = (float4*)(out + (size_t)(p0 + pbase) * NCH + 4 * cg);

    #pragma unroll 4
    for (int i = 0; i < TP / 4; i++) {
        const float4 q = pts[pbase + i];          // broadcast LDS.128
        const u64 qx = pack2(q.x, q.x);
        const u64 qy = pack2(q.y, q.y);
        const u64 qz = pack2(q.z, q.z);
        const u64 qw = pack2(q.w, q.w);

        // lin = W.x + b   (channel pairs)
        u64 l01 = fma2(wz01, qz, b01);
        u64 l23 = fma2(wz23, qz, b23);
        l01 = fma2(wy01, qy, l01);
        l23 = fma2(wy23, qy, l23);
        l01 = fma2(wx01, qx, l01);
        l23 = fma2(wx23, qx, l23);

        // e = a.x + ah*||x||^2 + cc    (log2-scaled exponent)
        u64 e01 = fma2(ah01, qw, cc01);
        u64 e23 = fma2(ah23, qw, cc23);
        e01 = fma2(az01, qz, e01);
        e23 = fma2(az23, qz, e23);
        e01 = fma2(ay01, qy, e01);
        e23 = fma2(ay23, qy, e23);
        e01 = fma2(ax01, qx, e01);
        e23 = fma2(ax23, qx, e23);

        float l0, l1, l2, l3, e0, e1, e2, e3;
        unpack2(l0, l1, l01); unpack2(l2, l3, l23);
        unpack2(e0, e1, e01); unpack2(e2, e3, e23);

        float t0, t1, t2, t3;
        asm("ex2.approx.f32 %0, %1;" : "=f"(t0) : "f"(e0));
        asm("ex2.approx.f32 %0, %1;" : "=f"(t1) : "f"(e1));
        asm("ex2.approx.f32 %0, %1;" : "=f"(t2) : "f"(e2));
        asm("ex2.approx.f32 %0, %1;" : "=f"(t3) : "f"(e3));

        float4 r;
        r.x = __sinf(l0) * t0;
        r.y = __sinf(l1) * t1;
        r.z = __sinf(l2) * t2;
        r.w = __sinf(l3) * t3;
        o[(size_t)i * (NCH / 4)] = r;             // STG.128, warp writes 512B contiguous
    }
}

extern "C" void kernel_launch(void* const* d_in, const int* in_sizes, int n_in,
                              void* d_out, int out_size)
{
    const float* x     = (const float*)d_in[0];  // (4, 65536, 3)
    const float* W     = (const float*)d_in[1];  // (256, 3)
    const float* b     = (const float*)d_in[2];  // (256,)
    const float* mu    = (const float*)d_in[3];  // (256, 3)
    const float* gamma = (const float*)d_in[4];  // (256,)
    float* out = (float*)d_out;                  // (4, 65536, 256)

    const int npts   = in_sizes[0] / 3;          // 262144
    const int ntiles = npts / TP;                // 4096

    gabor_kernel<<<ntiles, NCH>>>(x, W, b, mu, gamma, out);
}

// round 5
// speedup vs baseline: 1.0550x; 1.0402x over previous
#include <cuda_runtime.h>
#include <cstdint>

// GaborLayer: out[p, c] = sin(x_p . W_c + b_c) * exp(-0.5 * ||x_p - mu_c||^2 * gamma_c)
// 262144 points x 256 channels, fp32 out.
//
// R4: 2 channels/thread (9 u64 packed constants = 18 regs), f32x2 FFMA2 math,
// pre-splatted smem point tiles ({x,x,y,y},{z,z,w,w} as ulonglong2 -> no mov splats),
// __launch_bounds__(256,6) to force <=42 regs -> 6 blocks/SM (75% occ).
//
// exponent*log2e = a.x + ah*||x||^2 + cc,  a = g*mu, ah = -g/2, cc = ah*||mu||^2,
// g = gamma*log2e  -> one ex2.approx per element; sin via MUFU __sinf.

#define TP  64
#define NCH 256

typedef unsigned long long u64;

__device__ __forceinline__ u64 pack2(float lo, float hi) {
    u64 r; asm("mov.b64 %0, {%1, %2};" : "=l"(r) : "f"(lo), "f"(hi)); return r;
}
__device__ __forceinline__ void unpack2(float& lo, float& hi, u64 v) {
    asm("mov.b64 {%0, %1}, %2;" : "=f"(lo), "=f"(hi) : "l"(v));
}
__device__ __forceinline__ u64 fma2(u64 a, u64 b, u64 c) {
    u64 d; asm("fma.rn.f32x2 %0, %1, %2, %3;" : "=l"(d) : "l"(a), "l"(b), "l"(c)); return d;
}

__global__ __launch_bounds__(256, 6) void gabor_kernel(
    const float* __restrict__ x,
    const float* __restrict__ W,
    const float* __restrict__ b,
    const float* __restrict__ mu,
    const float* __restrict__ gamma,
    float* __restrict__ out)
{
    __shared__ float      raw[TP * 3];        // 768 B
    __shared__ ulonglong2 pts2[TP][2];        // [p][0]={x,x,y,y} [p][1]={z,z,w,w}, 2 KB

    const int tid = threadIdx.x;
    const int cg  = tid & 127;                // channel pair: channels 2cg, 2cg+1
    const int pl  = tid >> 7;                 // point lane 0..1

    // ---- per-thread constants for 2 channels, packed f32x2 (9 u64 = 18 regs) ----
    const float L2E = 1.4426950408889634f;
    const int c0 = 2 * cg, c1 = c0 + 1;
    const float m00 = mu[c0*3+0], m01 = mu[c0*3+1], m02 = mu[c0*3+2];
    const float m10 = mu[c1*3+0], m11 = mu[c1*3+1], m12 = mu[c1*3+2];
    const float g0 = gamma[c0] * L2E, g1 = gamma[c1] * L2E;

    const u64 wx = pack2(W[c0*3+0], W[c1*3+0]);
    const u64 wy = pack2(W[c0*3+1], W[c1*3+1]);
    const u64 wz = pack2(W[c0*3+2], W[c1*3+2]);
    const u64 bb = pack2(b[c0], b[c1]);
    const u64 ax = pack2(g0 * m00, g1 * m10);
    const u64 ay = pack2(g0 * m01, g1 * m11);
    const u64 az = pack2(g0 * m02, g1 * m12);
    const float ah0 = -0.5f * g0, ah1 = -0.5f * g1;
    const u64 ah = pack2(ah0, ah1);
    const u64 cc = pack2(ah0 * (m00*m00 + m01*m01 + m02*m02),
                         ah1 * (m10*m10 + m11*m11 + m12*m12));

    // ---- one tile of TP points per block ----
    const int p0 = blockIdx.x * TP;

    if (tid < TP * 3 / 4)
        ((float4*)raw)[tid] = ((const float4*)(x + (size_t)p0 * 3))[tid];
    __syncthreads();
    if (tid < TP) {
        const float v0 = raw[tid*3+0], v1 = raw[tid*3+1], v2 = raw[tid*3+2];
        const float w  = v0*v0 + v1*v1 + v2*v2;
        float4* d = (float4*)pts2[tid];
        d[0] = make_float4(v0, v0, v1, v1);
        d[1] = make_float4(v2, v2, w,  w);
    }
    __syncthreads();

    const int pbase = pl * (TP / 2);
    float2* o = (float2*)(out + (size_t)(p0 + pbase) * NCH + c0);

    #pragma unroll 8
    for (int i = 0; i < TP / 2; i++) {
        const ulonglong2 A = pts2[pbase + i][0];   // {x,x}, {y,y}  (LDS.128 broadcast)
        const ulonglong2 B = pts2[pbase + i][1];   // {z,z}, {w,w}

        // lin = W.x + b
        u64 l = fma2(wz, B.x, bb);
        l = fma2(wy, A.y, l);
        l = fma2(wx, A.x, l);

        // e = a.x + ah*||x||^2 + cc   (log2-scaled exponent)
        u64 e = fma2(ah, B.y, cc);
        e = fma2(az, B.x, e);
        e = fma2(ay, A.y, e);
        e = fma2(ax, A.x, e);

        float l0, l1, e0, e1;
        unpack2(l0, l1, l);
        unpack2(e0, e1, e);

        float t0, t1;
        asm("ex2.approx.f32 %0, %1;" : "=f"(t0) : "f"(e0));
        asm("ex2.approx.f32 %0, %1;" : "=f"(t1) : "f"(e1));

        float2 r;
        r.x = __sinf(l0) * t0;
        r.y = __sinf(l1) * t1;
        o[(size_t)i * (NCH / 2)] = r;              // STG.64, warp writes 256B contiguous
    }
}

extern "C" void kernel_launch(void* const* d_in, const int* in_sizes, int n_in,
                              void* d_out, int out_size)
{
    const float* x     = (const float*)d_in[0];  // (4, 65536, 3)
    const float* W     = (const float*)d_in[1];  // (256, 3)
    const float* b     = (const float*)d_in[2];  // (256,)
    const float* mu    = (const float*)d_in[3];  // (256, 3)
    const float* gamma = (const float*)d_in[4];  // (256,)
    float* out = (float*)d_out;                  // (4, 65536, 256)

    const int npts   = in_sizes[0] / 3;          // 262144
    const int ntiles = npts / TP;                // 4096

    gabor_kernel<<<ntiles, NCH>>>(x, W, b, mu, gamma, out);
}

// round 6
// speedup vs baseline: 1.0595x; 1.0043x over previous
#include <cuda_runtime.h>
#include <cstdint>

// GaborLayer: out[p, c] = sin(x_p . W_c + b_c) * exp(-0.5 * ||x_p - mu_c||^2 * gamma_c)
// 262144 points x 256 channels, fp32 out.
//
// R5: persistent blocks (grid = SMs*6), channel constants hoisted ONCE per block,
// grid-stride over point tiles. 2 channels/thread, f32x2 FFMA2 math, pre-splatted
// smem point tiles, st.global.cs streaming stores.
//
// exponent*log2e = a.x + ah*||x||^2 + cc,  a = g*mu, ah = -g/2, cc = ah*||mu||^2,
// g = gamma*log2e  -> one ex2.approx per element; sin via MUFU __sinf.

#define TP  64
#define NCH 256

typedef unsigned long long u64;

__device__ __forceinline__ u64 pack2(float lo, float hi) {
    u64 r; asm("mov.b64 %0, {%1, %2};" : "=l"(r) : "f"(lo), "f"(hi)); return r;
}
__device__ __forceinline__ void unpack2(float& lo, float& hi, u64 v) {
    asm("mov.b64 {%0, %1}, %2;" : "=f"(lo), "=f"(hi) : "l"(v));
}
__device__ __forceinline__ u64 fma2(u64 a, u64 b, u64 c) {
    u64 d; asm("fma.rn.f32x2 %0, %1, %2, %3;" : "=l"(d) : "l"(a), "l"(b), "l"(c)); return d;
}

__global__ __launch_bounds__(256, 6) void gabor_kernel(
    const float* __restrict__ x,
    const float* __restrict__ W,
    const float* __restrict__ b,
    const float* __restrict__ mu,
    const float* __restrict__ gamma,
    float* __restrict__ out,
    int ntiles)
{
    __shared__ float      raw[TP * 3];        // 768 B
    __shared__ ulonglong2 pts2[TP][2];        // [p][0]={x,x,y,y} [p][1]={z,z,w,w}, 2 KB

    const int tid = threadIdx.x;
    const int cg  = tid & 127;                // channel pair: channels 2cg, 2cg+1
    const int pl  = tid >> 7;                 // point lane 0..1

    // ---- per-thread constants for 2 channels, loaded ONCE per (persistent) block ----
    const float L2E = 1.4426950408889634f;
    const int c0 = 2 * cg, c1 = c0 + 1;
    const float m00 = mu[c0*3+0], m01 = mu[c0*3+1], m02 = mu[c0*3+2];
    const float m10 = mu[c1*3+0], m11 = mu[c1*3+1], m12 = mu[c1*3+2];
    const float g0 = gamma[c0] * L2E, g1 = gamma[c1] * L2E;

    const u64 wx = pack2(W[c0*3+0], W[c1*3+0]);
    const u64 wy = pack2(W[c0*3+1], W[c1*3+1]);
    const u64 wz = pack2(W[c0*3+2], W[c1*3+2]);
    const u64 bb = pack2(b[c0], b[c1]);
    const u64 ax = pack2(g0 * m00, g1 * m10);
    const u64 ay = pack2(g0 * m01, g1 * m11);
    const u64 az = pack2(g0 * m02, g1 * m12);
    const float ah0 = -0.5f * g0, ah1 = -0.5f * g1;
    const u64 ah = pack2(ah0, ah1);
    const u64 cc = pack2(ah0 * (m00*m00 + m01*m01 + m02*m02),
                         ah1 * (m10*m10 + m11*m11 + m12*m12));

    const int pbase = pl * (TP / 2);

    // ---- persistent tile loop ----
    for (int tile = blockIdx.x; tile < ntiles; tile += gridDim.x) {
        const int p0 = tile * TP;

        __syncthreads();                       // protect smem from previous tile's readers
        if (tid < TP * 3 / 4)
            ((float4*)raw)[tid] = ((const float4*)(x + (size_t)p0 * 3))[tid];
        __syncthreads();
        if (tid < TP) {
            const float v0 = raw[tid*3+0], v1 = raw[tid*3+1], v2 = raw[tid*3+2];
            const float w  = v0*v0 + v1*v1 + v2*v2;
            float4* d = (float4*)pts2[tid];
            d[0] = make_float4(v0, v0, v1, v1);
            d[1] = make_float4(v2, v2, w,  w);
        }
        __syncthreads();

        float* o = out + (size_t)(p0 + pbase) * NCH + c0;

        #pragma unroll 8
        for (int i = 0; i < TP / 2; i++) {
            const ulonglong2 A = pts2[pbase + i][0];   // {x,x}, {y,y}  (LDS.128 broadcast)
            const ulonglong2 B = pts2[pbase + i][1];   // {z,z}, {w,w}

            // lin = W.x + b
            u64 l = fma2(wz, B.x, bb);
            l = fma2(wy, A.y, l);
            l = fma2(wx, A.x, l);

            // e = a.x + ah*||x||^2 + cc   (log2-scaled exponent)
            u64 e = fma2(ah, B.y, cc);
            e = fma2(az, B.x, e);
            e = fma2(ay, A.y, e);
            e = fma2(ax, A.x, e);

            float l0, l1, e0, e1;
            unpack2(l0, l1, l);
            unpack2(e0, e1, e);

            float t0, t1;
            asm("ex2.approx.f32 %0, %1;" : "=f"(t0) : "f"(e0));
            asm("ex2.approx.f32 %0, %1;" : "=f"(t1) : "f"(e1));

            const float r0 = __sinf(l0) * t0;
            const float r1 = __sinf(l1) * t1;
            // streaming store (evict-first): output is write-once
            asm volatile("st.global.cs.v2.f32 [%0], {%1, %2};"
                         :: "l"(o + (size_t)i * NCH), "f"(r0), "f"(r1) : "memory");
        }
    }
}

extern "C" void kernel_launch(void* const* d_in, const int* in_sizes, int n_in,
                              void* d_out, int out_size)
{
    const float* x     = (const float*)d_in[0];  // (4, 65536, 3)
    const float* W     = (const float*)d_in[1];  // (256, 3)
    const float* b     = (const float*)d_in[2];  // (256,)
    const float* mu    = (const float*)d_in[3];  // (256, 3)
    const float* gamma = (const float*)d_in[4];  // (256,)
    float* out = (float*)d_out;                  // (4, 65536, 256)

    const int npts   = in_sizes[0] / 3;          // 262144
    const int ntiles = npts / TP;                // 4096

    static int nsm = 0;                          // device attr cache (no device mem)
    if (nsm == 0) {
        cudaDeviceGetAttribute(&nsm, cudaDevAttrMultiProcessorCount, 0);
        if (nsm <= 0) nsm = 148;
    }
    int grid = nsm * 6;
    if (grid > ntiles) grid = ntiles;

    gabor_kernel<<<grid, NCH>>>(x, W, b, mu, gamma, out, ntiles);
}